// round 1
// baseline (speedup 1.0000x reference)
#include <cuda_runtime.h>
#include <cstddef>

#define Mdim 256
#define Ndim 1024
#define Bdim 16384
#define Kiter 16
#define Pk 50u

// Scratch (allocation-free: __device__ globals)
__device__ float g_x [(size_t)Ndim * Bdim];   // x  (N,B)
__device__ float g_c [(size_t)Ndim * Bdim];   // c  (N,B)
__device__ float g_r [(size_t)Mdim * Bdim];   // r  (M,B)
__device__ float g_yT[(size_t)Mdim * Bdim];   // yT (M,B)

// ---------------------------------------------------------------------------
// Tiled SGEMM: C(rows x Bdim) = A @ X (- Sub), X is (Kd x Bdim) row-major.
// ATRANS=0: A[row][k] = A[row*strideA + k]   (phi)
// ATRANS=1: A[row][k] = A[k*strideA + row]   (W^T view of W)
// Tile: 128(m) x 128(b) x 16(k), 256 threads, 8x8 per thread.
// ---------------------------------------------------------------------------
template<int ATRANS>
__global__ void __launch_bounds__(256)
gemm_kernel(const float* __restrict__ A, const float* __restrict__ X,
            float* __restrict__ C, const float* __restrict__ Sub,
            int Kd, int strideA)
{
    __shared__ float As[16][128];
    __shared__ float Bs[16][128];
    const int tid = threadIdx.x;
    const int m0 = blockIdx.y * 128;
    const int b0 = blockIdx.x * 128;
    const int tx = tid & 15;
    const int ty = tid >> 4;

    float acc[8][8];
#pragma unroll
    for (int i = 0; i < 8; i++)
#pragma unroll
        for (int j = 0; j < 8; j++) acc[i][j] = 0.0f;

    for (int k0 = 0; k0 < Kd; k0 += 16) {
        // X tile: 16 x 128, float4, coalesced
#pragma unroll
        for (int l = 0; l < 2; l++) {
            int idx = tid + l * 256;        // 0..511
            int row = idx >> 5;             // 0..15
            int c4  = (idx & 31) << 2;      // 0..124
            float4 v = *(const float4*)(X + (size_t)(k0 + row) * Bdim + b0 + c4);
            *(float4*)(&Bs[row][c4]) = v;
        }
        if (ATRANS == 0) {
#pragma unroll
            for (int l = 0; l < 2; l++) {
                int idx = tid + l * 256;
                int m  = idx >> 2;          // 0..127
                int k4 = (idx & 3) << 2;    // 0,4,8,12
                float4 v = *(const float4*)(A + (size_t)(m0 + m) * strideA + k0 + k4);
                As[k4 + 0][m] = v.x;
                As[k4 + 1][m] = v.y;
                As[k4 + 2][m] = v.z;
                As[k4 + 3][m] = v.w;
            }
        } else {
#pragma unroll
            for (int l = 0; l < 2; l++) {
                int idx = tid + l * 256;
                int k  = idx >> 5;          // 0..15
                int r4 = (idx & 31) << 2;   // 0..124
                float4 v = *(const float4*)(A + (size_t)(k0 + k) * strideA + m0 + r4);
                *(float4*)(&As[k][r4]) = v;
            }
        }
        __syncthreads();
#pragma unroll
        for (int kk = 0; kk < 16; kk++) {
            float a[8], b[8];
#pragma unroll
            for (int i = 0; i < 8; i++) a[i] = As[kk][ty * 8 + i];
#pragma unroll
            for (int j = 0; j < 8; j++) b[j] = Bs[kk][tx * 8 + j];
#pragma unroll
            for (int i = 0; i < 8; i++)
#pragma unroll
                for (int j = 0; j < 8; j++)
                    acc[i][j] += a[i] * b[j];
        }
        __syncthreads();
    }

#pragma unroll
    for (int i = 0; i < 8; i++) {
        size_t m = (size_t)(m0 + ty * 8 + i);
#pragma unroll
        for (int jj = 0; jj < 2; jj++) {
            int bcol = b0 + tx * 8 + jj * 4;
            float4 vv;
            vv.x = acc[i][jj * 4 + 0];
            vv.y = acc[i][jj * 4 + 1];
            vv.z = acc[i][jj * 4 + 2];
            vv.w = acc[i][jj * 4 + 3];
            if (Sub != nullptr) {
                float4 s = *(const float4*)(Sub + m * Bdim + bcol);
                vv.x -= s.x; vv.y -= s.y; vv.z -= s.z; vv.w -= s.w;
            }
            *(float4*)(C + m * Bdim + bcol) = vv;
        }
    }
}

// ---------------------------------------------------------------------------
// Fused update: v = x - gamma*c; thr = 50th largest |v| per column (exact,
// 4-pass radix select on float bits); x = (|v|>thr) ? v : soft(v, theta*g(|x|)).
// One CTA per 32 batch columns; one warp selects 4 columns.
// Dynamic smem: v[1024][33] + hist[8][256] + thr[32] + sel[16]
// ---------------------------------------------------------------------------
#define UPD_SMEM_BYTES ((1024*33 + 2048 + 32 + 16) * 4)

__global__ void __launch_bounds__(256)
update_kernel(float* __restrict__ x, const float* __restrict__ c,
              const float* __restrict__ gammaArr, const float* __restrict__ thetaArr,
              int it)
{
    extern __shared__ unsigned char smraw[];
    float*    v    = (float*)smraw;                 // 1024*33 floats
    unsigned* hist = (unsigned*)(v + 1024 * 33);    // 8*256
    float*    thr  = (float*)(hist + 2048);         // 32
    unsigned* sel  = (unsigned*)(thr + 32);         // 16

    const int tid  = threadIdx.x;
    const int bl   = tid & 31;
    const int b    = blockIdx.x * 32 + bl;
    const float gamma = gammaArr[it];
    const float theta = thetaArr[it];

    // Phase 1: v = x - gamma*c (coalesced over b), stash in smem transposed
    for (int n = tid >> 5; n < 1024; n += 8) {
        float xv = x[(size_t)n * Bdim + b];
        float cv = c[(size_t)n * Bdim + b];
        v[n * 33 + bl] = xv - gamma * cv;
    }
    __syncthreads();

    // Phase 2: per-warp exact radix select of the Pk-th largest |v|
    const int w = tid >> 5;
    const int lane = tid & 31;
    unsigned* h = hist + w * 256;

    for (int cc = 0; cc < 4; cc++) {
        int col = w * 4 + cc;
        unsigned prefix = 0u, mask = 0u;
        unsigned k = Pk;
#pragma unroll
        for (int pass = 0; pass < 4; pass++) {
            int shift = 24 - 8 * pass;
#pragma unroll
            for (int i = lane; i < 256; i += 32) h[i] = 0u;
            __syncwarp();
            for (int n = lane; n < 1024; n += 32) {
                unsigned e = __float_as_uint(v[n * 33 + col]) & 0x7FFFFFFFu;
                if ((e & mask) == prefix)
                    atomicAdd(&h[(e >> shift) & 0xFFu], 1u);
            }
            __syncwarp();
            // lane owns bins [lane*8, lane*8+8): suffix sums within chunk
            unsigned loc[8];
            unsigned s = 0u;
#pragma unroll
            for (int r = 7; r >= 0; r--) { s += h[lane * 8 + r]; loc[r] = s; }
            // warp-wide suffix of chunk totals
            unsigned inc = s;
#pragma unroll
            for (int off = 1; off < 32; off <<= 1) {
                unsigned t = __shfl_down_sync(0xffffffffu, inc, off);
                if (lane + off < 32) inc += t;
            }
            unsigned above = inc - s;  // count of elems in strictly higher chunks
            // unique crossing: count_ge(d) >= k > count_ge(d+1)
#pragma unroll
            for (int r = 7; r >= 0; r--) {
                unsigned cge  = above + loc[r];
                unsigned cge1 = above + (r < 7 ? loc[r + 1] : 0u);
                if (cge >= k && cge1 < k) {
                    sel[w * 2]     = (unsigned)(lane * 8 + r);
                    sel[w * 2 + 1] = k - cge1;
                }
            }
            __syncwarp();
            unsigned d = sel[w * 2];
            k = sel[w * 2 + 1];
            prefix |= d << shift;
            mask   |= 0xFFu << shift;
            __syncwarp();
        }
        if (lane == 0) thr[col] = __uint_as_float(prefix);
    }
    __syncthreads();

    // Phase 3: soft-threshold + top-k keep; write x back (coalesced)
    for (int n = tid >> 5; n < 1024; n += 8) {
        float xv = x[(size_t)n * Bdim + b];      // old x (for g)
        float vv = v[n * 33 + bl];
        float av = fabsf(vv);
        float th = theta * (1.0f / (fabsf(xv) / 0.1f + 1.0f));
        float st = copysignf(fmaxf(av - th, 0.0f), vv);
        x[(size_t)n * Bdim + b] = (av > thr[bl]) ? vv : st;
    }
}

// ---------------------------------------------------------------------------
// Transposes & misc
// ---------------------------------------------------------------------------
__global__ void transpose_y_kernel(const float* __restrict__ y, float* __restrict__ yT)
{
    __shared__ float tile[32][33];
    int bx = blockIdx.x * 32;
    int mx = blockIdx.y * 32;
    int tx = threadIdx.x, ty = threadIdx.y;
    for (int i = ty; i < 32; i += 8)
        tile[i][tx] = y[(size_t)(bx + i) * Mdim + mx + tx];
    __syncthreads();
    for (int i = ty; i < 32; i += 8)
        yT[(size_t)(mx + i) * Bdim + bx + tx] = tile[tx][i];
}

__global__ void write_out_kernel(const float* __restrict__ x, float* __restrict__ out)
{
    __shared__ float tile[32][33];
    int bx = blockIdx.x * 32;
    int nx = blockIdx.y * 32;
    int tx = threadIdx.x, ty = threadIdx.y;
    for (int i = ty; i < 32; i += 8)
        tile[i][tx] = x[(size_t)(nx + i) * Bdim + bx + tx];
    __syncthreads();
    for (int i = ty; i < 32; i += 8)
        out[(size_t)(bx + i) * Ndim + nx + tx] = tile[tx][i];
}

__global__ void zero_kernel(float* __restrict__ p, size_t n)
{
    for (size_t i = (size_t)blockIdx.x * blockDim.x + threadIdx.x; i < n;
         i += (size_t)gridDim.x * blockDim.x)
        p[i] = 0.0f;
}

// ---------------------------------------------------------------------------
// Launch: yT once, zero x, then 16 x (GEMM1, GEMM2, update), output transpose.
// All plain kernel launches — graph-capturable, allocation-free.
// ---------------------------------------------------------------------------
extern "C" void kernel_launch(void* const* d_in, const int* in_sizes, int n_in,
                              void* d_out, int out_size)
{
    const float* y     = (const float*)d_in[0];
    const float* phi   = (const float*)d_in[1];
    const float* W     = (const float*)d_in[2];
    const float* gamma = (const float*)d_in[3];
    const float* theta = (const float*)d_in[4];
    float* out = (float*)d_out;

    float *xp, *cp, *rp, *ytp;
    cudaGetSymbolAddress((void**)&xp,  g_x);
    cudaGetSymbolAddress((void**)&cp,  g_c);
    cudaGetSymbolAddress((void**)&rp,  g_r);
    cudaGetSymbolAddress((void**)&ytp, g_yT);

    cudaFuncSetAttribute(update_kernel,
                         cudaFuncAttributeMaxDynamicSharedMemorySize,
                         UPD_SMEM_BYTES);

    transpose_y_kernel<<<dim3(Bdim / 32, Mdim / 32), dim3(32, 8)>>>(y, ytp);
    zero_kernel<<<2048, 256>>>(xp, (size_t)Ndim * Bdim);

    for (int it = 0; it < Kiter; it++) {
        // r = phi @ x - yT
        gemm_kernel<0><<<dim3(Bdim / 128, Mdim / 128), 256>>>(
            phi, xp, rp, ytp, Ndim, Ndim);
        // c = W^T @ r
        gemm_kernel<1><<<dim3(Bdim / 128, Ndim / 128), 256>>>(
            W, rp, cp, nullptr, Mdim, Ndim);
        // x = soft_threshold(x - gamma*c, theta*g(|x|), 50)
        update_kernel<<<Bdim / 32, 256, UPD_SMEM_BYTES>>>(xp, cp, gamma, theta, it);
    }

    // out = x.T, plus zero tail (the two (K,1) zero outputs)
    write_out_kernel<<<dim3(Bdim / 32, Ndim / 32), dim3(32, 8)>>>(xp, out);
    long long tail = (long long)out_size - (long long)Ndim * Bdim;
    if (tail > 0)
        zero_kernel<<<1, 256>>>(out + (size_t)Ndim * Bdim, (size_t)tail);
}

// round 2
// speedup vs baseline: 1.4902x; 1.4902x over previous
#include <cuda_runtime.h>
#include <cstdint>
#include <cstddef>

#define Mdim 256
#define Ndim 1024
#define Bdim 16384
#define Kiter 16
#define Pk 50u

// Scratch (allocation-free: __device__ globals)
__device__ float g_x   [(size_t)Ndim * Bdim];   // x   (N,B)
__device__ float g_c   [(size_t)Ndim * Bdim];   // c   (N,B)
__device__ float g_r   [(size_t)Mdim * Bdim];   // r   (M,B)
__device__ float g_yT  [(size_t)Mdim * Bdim];   // yT  (M,B)
__device__ float g_phiT[(size_t)Ndim * Mdim];   // phi^T (N,M)

// ---------------------------------------------------------------------------
// cp.async helpers
// ---------------------------------------------------------------------------
__device__ __forceinline__ void cp_async16(uint32_t saddr, const void* gaddr) {
    asm volatile("cp.async.ca.shared.global [%0], [%1], 16;\n"
                 :: "r"(saddr), "l"(gaddr));
}
#define CP_COMMIT() asm volatile("cp.async.commit_group;\n" ::: "memory")
#define CP_WAIT0()  asm volatile("cp.async.wait_group 0;\n" ::: "memory")

// ---------------------------------------------------------------------------
// Double-buffered SGEMM: C(rows x Bdim) = A(k-major) @ X (- Sub)
// A[k][row] = A[k*strideA + row].  Tile 128(m) x 128(b) x 16(k), 256 thr, 8x8.
// ---------------------------------------------------------------------------
__global__ void __launch_bounds__(256, 2)
gemm_kernel(const float* __restrict__ A, const float* __restrict__ X,
            float* __restrict__ C, const float* __restrict__ Sub,
            int Ktiles, int strideA)
{
    __shared__ __align__(16) float As[2][16][128];
    __shared__ __align__(16) float Bs[2][16][128];

    const int tid = threadIdx.x;
    const int m0 = blockIdx.y * 128;
    const int b0 = blockIdx.x * 128;
    const int tx = tid & 15;
    const int ty = tid >> 4;

    float acc[8][8];
#pragma unroll
    for (int i = 0; i < 8; i++)
#pragma unroll
        for (int j = 0; j < 8; j++) acc[i][j] = 0.0f;

    // stage loader: 16 rows x 128 floats per tile, 512 x 16B chunks, 2/thread
    auto load_stage = [&](int t, int buf) {
        int k0 = t * 16;
#pragma unroll
        for (int l = 0; l < 2; l++) {
            int ch  = tid + l * 256;       // 0..511
            int row = ch >> 5;             // 0..15
            int c4  = (ch & 31) << 2;      // 0..124
            cp_async16((uint32_t)__cvta_generic_to_shared(&As[buf][row][c4]),
                       A + (size_t)(k0 + row) * strideA + m0 + c4);
            cp_async16((uint32_t)__cvta_generic_to_shared(&Bs[buf][row][c4]),
                       X + (size_t)(k0 + row) * Bdim + b0 + c4);
        }
    };

    load_stage(0, 0);
    CP_COMMIT();

    for (int t = 0; t < Ktiles; t++) {
        CP_WAIT0();
        __syncthreads();
        if (t + 1 < Ktiles) {
            load_stage(t + 1, (t + 1) & 1);
            CP_COMMIT();
        }
        const int buf = t & 1;
#pragma unroll
        for (int kk = 0; kk < 16; kk++) {
            float a[8], b[8];
            *(float4*)&a[0] = *(const float4*)&As[buf][kk][ty * 8];
            *(float4*)&a[4] = *(const float4*)&As[buf][kk][ty * 8 + 4];
            *(float4*)&b[0] = *(const float4*)&Bs[buf][kk][tx * 8];
            *(float4*)&b[4] = *(const float4*)&Bs[buf][kk][tx * 8 + 4];
#pragma unroll
            for (int i = 0; i < 8; i++)
#pragma unroll
                for (int j = 0; j < 8; j++)
                    acc[i][j] += a[i] * b[j];
        }
    }

#pragma unroll
    for (int i = 0; i < 8; i++) {
        size_t m = (size_t)(m0 + ty * 8 + i);
#pragma unroll
        for (int jj = 0; jj < 2; jj++) {
            int bcol = b0 + tx * 8 + jj * 4;
            float4 vv;
            vv.x = acc[i][jj * 4 + 0];
            vv.y = acc[i][jj * 4 + 1];
            vv.z = acc[i][jj * 4 + 2];
            vv.w = acc[i][jj * 4 + 3];
            if (Sub != nullptr) {
                float4 s = *(const float4*)(Sub + m * Bdim + bcol);
                vv.x -= s.x; vv.y -= s.y; vv.z -= s.z; vv.w -= s.w;
            }
            *(float4*)(C + m * Bdim + bcol) = vv;
        }
    }
}

// ---------------------------------------------------------------------------
// Fused update: v = x - gamma*c; thr = Pk-th largest |v| per column (exact
// 4-pass radix select on fp32 bits); x = (|v|>thr) ? v : soft(v, theta*g(|x|)).
// 8 batch columns per CTA, one warp per column for the select.
// Static smem: v[1024*9] + hist[8*256] + thr[8] + sel[16]  (~45KB)
// ---------------------------------------------------------------------------
__global__ void __launch_bounds__(256)
update_kernel(float* __restrict__ x, const float* __restrict__ c,
              const float* __restrict__ gammaArr, const float* __restrict__ thetaArr,
              int it)
{
    __shared__ float    v[1024 * 9];      // v[n*9 + b8]
    __shared__ unsigned hist[8 * 256];
    __shared__ float    thr[8];
    __shared__ unsigned sel[16];

    const int tid  = threadIdx.x;
    const int b8t  = tid & 7;
    const int bbase = blockIdx.x * 8;
    const float gamma = gammaArr[it];
    const float theta = thetaArr[it];

    // Phase 1: v = x - gamma*c (32B-sector coalesced over b)
#pragma unroll
    for (int l = 0; l < 32; l++) {
        int idx = tid + l * 256;          // 0..8191
        int n   = idx >> 3;
        int bb  = idx & 7;
        size_t g = (size_t)n * Bdim + bbase + bb;
        v[n * 9 + bb] = x[g] - gamma * c[g];
    }
    __syncthreads();

    // Phase 2: per-warp exact radix select (warp w owns column w)
    const int w = tid >> 5;
    const int lane = tid & 31;
    unsigned* h = hist + w * 256;

    unsigned prefix = 0u, mask = 0u;
    unsigned k = Pk;
#pragma unroll
    for (int pass = 0; pass < 4; pass++) {
        int shift = 24 - 8 * pass;
#pragma unroll
        for (int i = lane; i < 256; i += 32) h[i] = 0u;
        __syncwarp();
        for (int n = lane; n < 1024; n += 32) {
            unsigned e = __float_as_uint(v[n * 9 + w]) & 0x7FFFFFFFu;
            if ((e & mask) == prefix)
                atomicAdd(&h[(e >> shift) & 0xFFu], 1u);
        }
        __syncwarp();
        // lane owns bins [lane*8, lane*8+8): suffix sums within chunk
        unsigned loc[8];
        unsigned s = 0u;
#pragma unroll
        for (int r = 7; r >= 0; r--) { s += h[lane * 8 + r]; loc[r] = s; }
        // warp-wide suffix of chunk totals
        unsigned inc = s;
#pragma unroll
        for (int off = 1; off < 32; off <<= 1) {
            unsigned t = __shfl_down_sync(0xffffffffu, inc, off);
            if (lane + off < 32) inc += t;
        }
        unsigned above = inc - s;
        // unique crossing: count_ge(d) >= k > count_ge(d+1)
#pragma unroll
        for (int r = 7; r >= 0; r--) {
            unsigned cge  = above + loc[r];
            unsigned cge1 = above + (r < 7 ? loc[r + 1] : 0u);
            if (cge >= k && cge1 < k) {
                sel[w * 2]     = (unsigned)(lane * 8 + r);
                sel[w * 2 + 1] = k - cge1;
            }
        }
        __syncwarp();
        unsigned d = sel[w * 2];
        k = sel[w * 2 + 1];
        prefix |= d << shift;
        mask   |= 0xFFu << shift;
        __syncwarp();
    }
    if (lane == 0) thr[w] = __uint_as_float(prefix);
    __syncthreads();

    // Phase 3: soft-threshold + top-k keep; write x back
#pragma unroll
    for (int l = 0; l < 32; l++) {
        int idx = tid + l * 256;
        int n   = idx >> 3;
        int bb  = idx & 7;
        size_t g = (size_t)n * Bdim + bbase + bb;
        float xv = x[g];                  // old x (for g(|x|))
        float vv = v[n * 9 + bb];
        float av = fabsf(vv);
        float th = theta * (1.0f / (fabsf(xv) / 0.1f + 1.0f));
        float st = copysignf(fmaxf(av - th, 0.0f), vv);
        x[g] = (av > thr[bb]) ? vv : st;
    }
}

// ---------------------------------------------------------------------------
// Transposes & misc
// ---------------------------------------------------------------------------
__global__ void transpose_y_kernel(const float* __restrict__ y, float* __restrict__ yT)
{
    __shared__ float tile[32][33];
    int bx = blockIdx.x * 32;
    int mx = blockIdx.y * 32;
    int tx = threadIdx.x, ty = threadIdx.y;
    for (int i = ty; i < 32; i += 8)
        tile[i][tx] = y[(size_t)(bx + i) * Mdim + mx + tx];
    __syncthreads();
    for (int i = ty; i < 32; i += 8)
        yT[(size_t)(mx + i) * Bdim + bx + tx] = tile[tx][i];
}

__global__ void transpose_phi_kernel(const float* __restrict__ phi, float* __restrict__ phiT)
{
    __shared__ float tile[32][33];
    int nx = blockIdx.x * 32;   // N dim
    int mx = blockIdx.y * 32;   // M dim
    int tx = threadIdx.x, ty = threadIdx.y;
    for (int i = ty; i < 32; i += 8)
        tile[i][tx] = phi[(size_t)(mx + i) * Ndim + nx + tx];
    __syncthreads();
    for (int i = ty; i < 32; i += 8)
        phiT[(size_t)(nx + i) * Mdim + mx + tx] = tile[tx][i];
}

__global__ void write_out_kernel(const float* __restrict__ x, float* __restrict__ out)
{
    __shared__ float tile[32][33];
    int bx = blockIdx.x * 32;
    int nx = blockIdx.y * 32;
    int tx = threadIdx.x, ty = threadIdx.y;
    for (int i = ty; i < 32; i += 8)
        tile[i][tx] = x[(size_t)(nx + i) * Bdim + bx + tx];
    __syncthreads();
    for (int i = ty; i < 32; i += 8)
        out[(size_t)(bx + i) * Ndim + nx + tx] = tile[tx][i];
}

__global__ void zero_kernel(float* __restrict__ p, size_t n)
{
    for (size_t i = (size_t)blockIdx.x * blockDim.x + threadIdx.x; i < n;
         i += (size_t)gridDim.x * blockDim.x)
        p[i] = 0.0f;
}

// ---------------------------------------------------------------------------
// Launch
// ---------------------------------------------------------------------------
extern "C" void kernel_launch(void* const* d_in, const int* in_sizes, int n_in,
                              void* d_out, int out_size)
{
    const float* y     = (const float*)d_in[0];
    const float* phi   = (const float*)d_in[1];
    const float* W     = (const float*)d_in[2];
    const float* gamma = (const float*)d_in[3];
    const float* theta = (const float*)d_in[4];
    float* out = (float*)d_out;

    float *xp, *cp, *rp, *ytp, *ptp;
    cudaGetSymbolAddress((void**)&xp,  g_x);
    cudaGetSymbolAddress((void**)&cp,  g_c);
    cudaGetSymbolAddress((void**)&rp,  g_r);
    cudaGetSymbolAddress((void**)&ytp, g_yT);
    cudaGetSymbolAddress((void**)&ptp, g_phiT);

    transpose_y_kernel  <<<dim3(Bdim / 32, Mdim / 32), dim3(32, 8)>>>(y, ytp);
    transpose_phi_kernel<<<dim3(Ndim / 32, Mdim / 32), dim3(32, 8)>>>(phi, ptp);
    zero_kernel<<<2048, 256>>>(xp, (size_t)Ndim * Bdim);

    for (int it = 0; it < Kiter; it++) {
        // r = phi @ x - yT   (A = phiT, k-major over N)
        gemm_kernel<<<dim3(Bdim / 128, Mdim / 128), 256>>>(
            ptp, xp, rp, ytp, Ndim / 16, Mdim);
        // c = W^T @ r        (A = W, k-major over M)
        gemm_kernel<<<dim3(Bdim / 128, Ndim / 128), 256>>>(
            W, rp, cp, nullptr, Mdim / 16, Ndim);
        // x = soft_threshold(x - gamma*c, theta*g(|x|), 50)
        update_kernel<<<Bdim / 8, 256>>>(xp, cp, gamma, theta, it);
    }

    // out = x.T, plus zero tail (the two (K,1) zero outputs)
    write_out_kernel<<<dim3(Bdim / 32, Ndim / 32), dim3(32, 8)>>>(xp, out);
    long long tail = (long long)out_size - (long long)Ndim * Bdim;
    if (tail > 0)
        zero_kernel<<<1, 256>>>(out + (size_t)Ndim * Bdim, (size_t)tail);
}

// round 4
// speedup vs baseline: 2.0360x; 1.3662x over previous
#include <cuda_runtime.h>
#include <cstdint>
#include <cstddef>

#define Mdim 256
#define Ndim 1024
#define Bdim 16384
#define Kiter 16
#define Pk 50u

// ---------------------------------------------------------------------------
// Scratch (allocation-free __device__ globals). Batch-major layout:
// x (B,N), r (B,M), c (B,N). W^T (N,M) K-major. phi used natively (M,N).
// ---------------------------------------------------------------------------
__device__ float g_x [(size_t)Bdim * Ndim];
__device__ float g_r [(size_t)Bdim * Mdim];
__device__ float g_c [(size_t)Bdim * Ndim];
__device__ float g_wt[(size_t)Ndim * Mdim];

// ---------------------------------------------------------------------------
// PTX helpers (all plain-sm_103-legal: cp.async sm_80+, mma.sync tf32 sm_80+)
// ---------------------------------------------------------------------------
__device__ __forceinline__ void cp_async16(uint32_t saddr, const void* gaddr) {
    asm volatile("cp.async.cg.shared.global [%0], [%1], 16;\n"
                 :: "r"(saddr), "l"(gaddr));
}
#define CP_COMMIT() asm volatile("cp.async.commit_group;\n" ::: "memory")
#define CP_WAIT0()  asm volatile("cp.async.wait_group 0;\n" ::: "memory")
#define CP_WAIT1()  asm volatile("cp.async.wait_group 1;\n" ::: "memory")

__device__ __forceinline__ void split_tf32(float v, uint32_t& hi, uint32_t& lo) {
    uint32_t h;
    asm("cvt.rna.tf32.f32 %0, %1;" : "=r"(h) : "f"(v));
    float hf = __uint_as_float(h);
    asm("cvt.rna.tf32.f32 %0, %1;" : "=r"(lo) : "f"(v - hf));
    hi = h;
}

__device__ __forceinline__ void mma_tf32(float* d, const uint32_t* a,
                                         const uint32_t* b) {
    asm volatile(
        "mma.sync.aligned.m16n8k8.row.col.f32.tf32.tf32.f32 "
        "{%0,%1,%2,%3}, {%4,%5,%6,%7}, {%8,%9}, {%0,%1,%2,%3};"
        : "+f"(d[0]), "+f"(d[1]), "+f"(d[2]), "+f"(d[3])
        : "r"(a[0]), "r"(a[1]), "r"(a[2]), "r"(a[3]),
          "r"(b[0]), "r"(b[1]));
}

// ---------------------------------------------------------------------------
// TF32x3 GEMM: D(B x Nrows) = A(B,Kd) @ Bm(Nrows,Kd)^T  [minus Sub if SUBY]
// A, Bm fp32 K-major; split to tf32 hi/lo at fragment-load time.
// Tile 128(b) x 128(n) x 16(k), 256 threads (8 warps, 2x4), warp = 64x32.
// smem per stage: A 128x20f + B 128x20f (pad 20 -> conflict-free frags).
// ---------------------------------------------------------------------------
#define KTILE 16
#define ROWPAD 20
#define OP_FLOATS (128 * ROWPAD)             // 2560 floats per operand
#define STAGE_BYTES (2 * OP_FLOATS * 4)      // 20480 B (A + B)
#define GEMM_SMEM (2 * STAGE_BYTES)          // 40960 B (double buffer)

template<int SUBY>
__global__ void __launch_bounds__(256)
gemm_tc(const float* __restrict__ A, const float* __restrict__ Bm,
        float* __restrict__ D, const float* __restrict__ Sub,
        int Kd, int CStride)
{
    extern __shared__ float sm[];
    const int tid  = threadIdx.x;
    const int wid  = tid >> 5;
    const int lane = tid & 31;
    const int gid  = lane >> 2;
    const int tig  = lane & 3;
    const int wm   = wid >> 2;       // 0..1 -> 64-row strip
    const int wn   = wid & 3;        // 0..3 -> 32-col strip
    const int b0   = blockIdx.y * 128;
    const int n0   = blockIdx.x * 128;
    const uint32_t smbase = (uint32_t)__cvta_generic_to_shared(sm);

    float acc[4][4][4];
#pragma unroll
    for (int i = 0; i < 4; i++)
#pragma unroll
        for (int j = 0; j < 4; j++)
#pragma unroll
            for (int q = 0; q < 4; q++) acc[i][j][q] = 0.0f;

    auto load_stage = [&](int t, int buf) {
        const int k0 = t * KTILE;
        const uint32_t sb = smbase + buf * STAGE_BYTES;
#pragma unroll
        for (int l = 0; l < 2; l++) {
            int c   = tid + l * 256;            // 0..511
            int row = c >> 2;                   // 0..127
            int ch  = c & 3;                    // 0..3 (16B chunks of 16 floats)
            cp_async16(sb + row * (ROWPAD * 4) + ch * 16,
                       A + (size_t)(b0 + row) * Kd + k0 + ch * 4);
            cp_async16(sb + OP_FLOATS * 4 + row * (ROWPAD * 4) + ch * 16,
                       Bm + (size_t)(n0 + row) * Kd + k0 + ch * 4);
        }
    };

    const int T = Kd / KTILE;
    load_stage(0, 0);
    CP_COMMIT();

    for (int t = 0; t < T; t++) {
        const int buf = t & 1;
        if (t + 1 < T) {
            load_stage(t + 1, buf ^ 1);
            CP_COMMIT();
            CP_WAIT1();
        } else {
            CP_WAIT0();
        }
        __syncthreads();

        const float* As = sm + buf * (STAGE_BYTES / 4);
        const float* Bs = As + OP_FLOATS;

#pragma unroll
        for (int s = 0; s < 2; s++) {
            const int kb = s * 8;
            uint32_t bhi[4][2], blo[4][2];
#pragma unroll
            for (int nt = 0; nt < 4; nt++) {
                int n = wn * 32 + nt * 8 + gid;
                float v0 = Bs[n * ROWPAD + kb + tig];
                float v1 = Bs[n * ROWPAD + kb + tig + 4];
                split_tf32(v0, bhi[nt][0], blo[nt][0]);
                split_tf32(v1, bhi[nt][1], blo[nt][1]);
            }
#pragma unroll
            for (int mt = 0; mt < 4; mt++) {
                int m = wm * 64 + mt * 16 + gid;
                float v0 = As[m * ROWPAD + kb + tig];
                float v1 = As[(m + 8) * ROWPAD + kb + tig];
                float v2 = As[m * ROWPAD + kb + tig + 4];
                float v3 = As[(m + 8) * ROWPAD + kb + tig + 4];
                uint32_t ahi[4], alo[4];
                split_tf32(v0, ahi[0], alo[0]);
                split_tf32(v1, ahi[1], alo[1]);
                split_tf32(v2, ahi[2], alo[2]);
                split_tf32(v3, ahi[3], alo[3]);
#pragma unroll
                for (int nt = 0; nt < 4; nt++) {
                    mma_tf32(acc[mt][nt], ahi, bhi[nt]);
                    mma_tf32(acc[mt][nt], ahi, blo[nt]);
                    mma_tf32(acc[mt][nt], alo, bhi[nt]);
                }
            }
        }
        __syncthreads();
    }

    // Epilogue: fragment layout c0:(r,2c) c1:(r,2c+1) c2:(r+8,2c) c3:(r+8,2c+1)
#pragma unroll
    for (int mt = 0; mt < 4; mt++) {
        int r0 = b0 + wm * 64 + mt * 16 + gid;
#pragma unroll
        for (int nt = 0; nt < 4; nt++) {
            int col = n0 + wn * 32 + nt * 8 + tig * 2;
            float2 v0 = make_float2(acc[mt][nt][0], acc[mt][nt][1]);
            float2 v1 = make_float2(acc[mt][nt][2], acc[mt][nt][3]);
            if (SUBY) {
                float2 y0 = *(const float2*)(Sub + (size_t)r0 * CStride + col);
                float2 y1 = *(const float2*)(Sub + (size_t)(r0 + 8) * CStride + col);
                v0.x -= y0.x; v0.y -= y0.y;
                v1.x -= y1.x; v1.y -= y1.y;
            }
            *(float2*)(D + (size_t)r0 * CStride + col) = v0;
            *(float2*)(D + (size_t)(r0 + 8) * CStride + col) = v1;
        }
    }
}

// ---------------------------------------------------------------------------
// Fused update on (B,N): one warp per batch row.
// v = x - gamma*c; thr = exact Pk-th largest |v| (4-pass radix select on fp32
// bits); xout = (|v|>thr) ? v : soft(v, theta*g(|x|)).
// ---------------------------------------------------------------------------
__global__ void __launch_bounds__(256)
update_kernel(const float* __restrict__ x, float* __restrict__ xout,
              const float* __restrict__ c,
              const float* __restrict__ gammaArr,
              const float* __restrict__ thetaArr, int it)
{
    __shared__ float    v[8][1024];
    __shared__ unsigned hist[8][256];

    const int tid  = threadIdx.x;
    const int w    = tid >> 5;
    const int lane = tid & 31;
    const size_t base = ((size_t)blockIdx.x * 8 + w) * Ndim;
    const float gamma = gammaArr[it];
    const float theta = thetaArr[it];

    float xabs[32];
#pragma unroll
    for (int i = 0; i < 8; i++) {
        int n = i * 128 + lane * 4;
        float4 xv = *(const float4*)(x + base + n);
        float4 cc = *(const float4*)(c + base + n);
        xabs[i * 4 + 0] = fabsf(xv.x);
        xabs[i * 4 + 1] = fabsf(xv.y);
        xabs[i * 4 + 2] = fabsf(xv.z);
        xabs[i * 4 + 3] = fabsf(xv.w);
        float4 vv;
        vv.x = xv.x - gamma * cc.x;
        vv.y = xv.y - gamma * cc.y;
        vv.z = xv.z - gamma * cc.z;
        vv.w = xv.w - gamma * cc.w;
        *(float4*)(&v[w][n]) = vv;
    }
    __syncwarp();

    // exact radix select of Pk-th largest |v| over 1024 values
    unsigned prefix = 0u, mask = 0u, k = Pk;
    unsigned* h = hist[w];
#pragma unroll
    for (int pass = 0; pass < 4; pass++) {
        const int shift = 24 - 8 * pass;
#pragma unroll
        for (int i = lane; i < 256; i += 32) h[i] = 0u;
        __syncwarp();
        for (int n = lane; n < 1024; n += 32) {
            unsigned e = __float_as_uint(v[w][n]) & 0x7FFFFFFFu;
            if ((e & mask) == prefix)
                atomicAdd(&h[(e >> shift) & 0xFFu], 1u);
        }
        __syncwarp();
        unsigned loc[8];
        unsigned s = 0u;
#pragma unroll
        for (int r = 7; r >= 0; r--) { s += h[lane * 8 + r]; loc[r] = s; }
        unsigned inc = s;
#pragma unroll
        for (int off = 1; off < 32; off <<= 1) {
            unsigned t = __shfl_down_sync(0xffffffffu, inc, off);
            if (lane + off < 32) inc += t;
        }
        const unsigned above = inc - s;
        unsigned dfound = 0u, kfound = 0u;
        bool found = false;
#pragma unroll
        for (int r = 7; r >= 0; r--) {
            unsigned cge  = above + loc[r];
            unsigned cge1 = above + (r < 7 ? loc[r + 1] : 0u);
            if (cge >= k && cge1 < k) {
                dfound = (unsigned)(lane * 8 + r);
                kfound = k - cge1;
                found = true;
            }
        }
        unsigned bal = __ballot_sync(0xffffffffu, found);
        int src = __ffs(bal) - 1;
        dfound = __shfl_sync(0xffffffffu, dfound, src);
        kfound = __shfl_sync(0xffffffffu, kfound, src);
        k = kfound;
        prefix |= dfound << shift;
        mask   |= 0xFFu << shift;
        __syncwarp();
    }
    const float thrv = __uint_as_float(prefix);

#pragma unroll
    for (int i = 0; i < 8; i++) {
        int n = i * 128 + lane * 4;
        float4 vv = *(const float4*)(&v[w][n]);
        float4 o;
        float* vp = &vv.x;
        float* op = &o.x;
#pragma unroll
        for (int jc = 0; jc < 4; jc++) {
            float val = vp[jc];
            float av = fabsf(val);
            float th = theta * (1.0f / (xabs[i * 4 + jc] / 0.1f + 1.0f));
            float st = copysignf(fmaxf(av - th, 0.0f), val);
            op[jc] = (av > thrv) ? val : st;
        }
        *(float4*)(xout + base + n) = o;
    }
}

// ---------------------------------------------------------------------------
// Prep / misc kernels
// ---------------------------------------------------------------------------
__global__ void transpose_w_kernel(const float* __restrict__ W,
                                   float* __restrict__ wt)
{
    __shared__ float tile[32][33];
    int n0 = blockIdx.x * 32;
    int m0 = blockIdx.y * 32;
    int tx = threadIdx.x, ty = threadIdx.y;
    for (int i = ty; i < 32; i += 8)
        tile[i][tx] = W[(size_t)(m0 + i) * Ndim + n0 + tx];
    __syncthreads();
    for (int i = ty; i < 32; i += 8)
        wt[(size_t)(n0 + i) * Mdim + m0 + tx] = tile[tx][i];
}

__global__ void neg_copy_kernel(const float* __restrict__ src,
                                float* __restrict__ dst, size_t n)
{
    size_t i = ((size_t)blockIdx.x * blockDim.x + threadIdx.x) * 4;
    if (i < n) {
        float4 v = *(const float4*)(src + i);
        v.x = -v.x; v.y = -v.y; v.z = -v.z; v.w = -v.w;
        *(float4*)(dst + i) = v;
    }
}

__global__ void zero_kernel(float* __restrict__ p, size_t n)
{
    for (size_t i = (size_t)blockIdx.x * blockDim.x + threadIdx.x; i < n;
         i += (size_t)gridDim.x * blockDim.x)
        p[i] = 0.0f;
}

// ---------------------------------------------------------------------------
// Launch
// ---------------------------------------------------------------------------
extern "C" void kernel_launch(void* const* d_in, const int* in_sizes, int n_in,
                              void* d_out, int out_size)
{
    const float* y     = (const float*)d_in[0];
    const float* phi   = (const float*)d_in[1];
    const float* W     = (const float*)d_in[2];
    const float* gamma = (const float*)d_in[3];
    const float* theta = (const float*)d_in[4];
    float* out = (float*)d_out;

    float *xp, *rp, *cp, *wtp;
    cudaGetSymbolAddress((void**)&xp,  g_x);
    cudaGetSymbolAddress((void**)&rp,  g_r);
    cudaGetSymbolAddress((void**)&cp,  g_c);
    cudaGetSymbolAddress((void**)&wtp, g_wt);

    transpose_w_kernel<<<dim3(Ndim / 32, Mdim / 32), dim3(32, 8)>>>(W, wtp);
    zero_kernel<<<2048, 256>>>(xp, (size_t)Bdim * Ndim);

    for (int it = 0; it < Kiter; it++) {
        // r = x @ phi^T - y   (iteration 0: x = 0 -> r = -y)
        if (it == 0) {
            neg_copy_kernel<<<(Bdim * Mdim / 4 + 255) / 256, 256>>>(
                y, rp, (size_t)Bdim * Mdim);
        } else {
            gemm_tc<1><<<dim3(Mdim / 128, Bdim / 128), 256, GEMM_SMEM>>>(
                xp, phi, rp, y, Ndim, Mdim);
        }
        // c = r @ W   (B operand = W^T, K-major over M)
        gemm_tc<0><<<dim3(Ndim / 128, Bdim / 128), 256, GEMM_SMEM>>>(
            rp, wtp, cp, nullptr, Mdim, Ndim);
        // x = soft_threshold(x - gamma*c, theta*g(|x|), 50)
        float* xout = (it == Kiter - 1) ? out : xp;
        update_kernel<<<Bdim / 8, 256>>>(xp, xout, cp, gamma, theta, it);
    }

    // zero the tail (the two (K,1) zero outputs appended to x)
    long long tail = (long long)out_size - (long long)Ndim * Bdim;
    if (tail > 0)
        zero_kernel<<<1, 256>>>(out + (size_t)Ndim * Bdim, (size_t)tail);
}